// round 6
// baseline (speedup 1.0000x reference)
#include <cuda_runtime.h>
#include <cuda_bf16.h>
#include <math.h>
#include <stdint.h>

#define NH 6
#define NB 512
#define ND 2048
#define NC 1000
#define NP 1024
#define TAU 0.5f

#define BK 64                    // int8 k-elems per stage (64-byte rows)
#define NITER (ND / BK)          // 32
#define STAGES 3
#define STG_BYTES (24 * 1024)    // A1 4K | A0 4K | B1 8K | B0 8K
#define GSMEM (STAGES * STG_BYTES)

// scales: feats Sa = 2^-4 (range +-7.97), W Sb = 2^-8 (range +-0.498)
#define INV_SA 16.0f
#define INV_SB 256.0f
#define S_MAIN 2.44140625e-4f        // Sa*Sb = 2^-12
#define S_CORR 9.5367431640625e-7f   // Sa*Sb/256 = 2^-20

// ------------------------- scratch ------------------------------------------
__device__ char g_A1[NH * NB * ND];
__device__ char g_A0[NH * NB * ND];
__device__ char g_B1[NH * NP * ND];   // [h][n][k]
__device__ char g_B0[NH * NP * ND];
__device__ float g_logits[NH * NB * NC];
__device__ float g_conf[NH * NB];
__device__ float g_logZ[NH * NB];
__device__ int   g_amax[NH * NB];
__device__ float g_loss[NB];
__device__ float g_corr[NB];

// ------------------------- helpers ------------------------------------------
__device__ __forceinline__ uint32_t smem_u32(const void* p) {
    uint32_t a;
    asm("{ .reg .u64 t; cvta.to.shared.u64 t, %1; cvt.u32.u64 %0, t; }" : "=r"(a) : "l"(p));
    return a;
}
__device__ __forceinline__ void cp16(uint32_t dst, const void* src) {
    asm volatile("cp.async.cg.shared.global [%0], [%1], 16;\n" :: "r"(dst), "l"(src) : "memory");
}
__device__ __forceinline__ void cp_commit() {
    asm volatile("cp.async.commit_group;\n" ::: "memory");
}
template<int N> __device__ __forceinline__ void cp_wait() {
    asm volatile("cp.async.wait_group %0;\n" :: "n"(N) : "memory");
}
__device__ __forceinline__ uint32_t swz_addr(uint32_t base, int row, int colb) {
    return base + (uint32_t)(row * 64 + (colb ^ ((row & 6) << 3)));
}
#define LDSM4(r, a) \
    asm volatile("ldmatrix.sync.aligned.m8n8.x4.shared.b16 {%0,%1,%2,%3}, [%4];" \
        : "=r"((r)[0]), "=r"((r)[1]), "=r"((r)[2]), "=r"((r)[3]) : "r"(a))
#define IMMA16832(c, a, b0, b1) \
    asm volatile("mma.sync.aligned.m16n8k32.row.col.s32.s8.s8.s32 " \
        "{%0,%1,%2,%3}, {%4,%5,%6,%7}, {%8,%9}, {%0,%1,%2,%3};" \
        : "+r"((c)[0]), "+r"((c)[1]), "+r"((c)[2]), "+r"((c)[3]) \
        : "r"((a)[0]), "r"((a)[1]), "r"((a)[2]), "r"((a)[3]), "r"(b0), "r"(b1))

// fp32 -> 2 int8 limbs (radix 256): x ~= (q1 + q0/256)/invS
__device__ __forceinline__ void split8(float x, float invS, char& c1, char& c0) {
    float q = x * invS;
    q = fminf(fmaxf(q, -127.496f), 127.496f);
    float q1 = rintf(q);
    float q0 = rintf((q - q1) * 256.f);
    q0 = fminf(fmaxf(q0, -127.f), 127.f);
    c1 = (char)(int)q1;
    c0 = (char)(int)q0;
}

// ------------------------- merged conversion kernel --------------------------
#define NA_BLK (NH * NB * ND / 4 / 256)      // 6144

__global__ __launch_bounds__(256) void conv_all(const float* __restrict__ x,
                                                const float* __restrict__ W) {
    const int tid = threadIdx.x;
    if (blockIdx.x < NA_BLK) {
        const int i = blockIdx.x * 256 + tid;
        float4 v = ((const float4*)x)[i];
        char h0, l0, h1, l1, h2, l2, h3, l3;
        split8(v.x, INV_SA, h0, l0);
        split8(v.y, INV_SA, h1, l1);
        split8(v.z, INV_SA, h2, l2);
        split8(v.w, INV_SA, h3, l3);
        ((char4*)g_A1)[i] = make_char4(h0, h1, h2, h3);
        ((char4*)g_A0)[i] = make_char4(l0, l1, l2, l3);
        return;
    }
    // B role: W [h][k][n] fp32 -> g_B{1,0} [h][n(1024)][k] int8
    __shared__ float t[32][33];
    const int bi = blockIdx.x - NA_BLK;
    const int n0 = (bi & 31) * 32;
    const int k0 = ((bi >> 5) & 63) * 32;
    const int h  = bi >> 11;

    const int tx = tid & 31, ty = tid >> 5;
    #pragma unroll
    for (int i = 0; i < 4; i++) {
        int k = k0 + ty + 8 * i;
        int n = n0 + tx;
        t[ty + 8 * i][tx] = (n < NC) ? W[((size_t)h * ND + k) * NC + n] : 0.f;
    }
    __syncthreads();

    const int u  = tid & 127;
    const int nn = u >> 2;
    const int kg = u & 3;
    const int isLo = tid >> 7;
    char vals[8];
    #pragma unroll
    for (int j = 0; j < 8; j++) {
        char c1, c0;
        split8(t[kg * 8 + j][nn], INV_SB, c1, c0);
        vals[j] = isLo ? c0 : c1;
    }
    char* dst = (isLo ? g_B0 : g_B1) + ((size_t)h * NP + n0 + nn) * ND + k0 + kg * 8;
    *(uint2*)dst = *(uint2*)vals;
}

// ------------------------- int8 limb GEMM -----------------------------------
// CTA 64(M)x128(N), 4 warps (warp tile 64x32), BK=64 int8, 3-stage cp.async.
__global__ void __launch_bounds__(128, 3) gemm_mma(const float* __restrict__ bias) {
    extern __shared__ char sm[];
    const uint32_t sb = smem_u32(sm);
    const int tid = threadIdx.x;
    const int wid = tid >> 5, l = tid & 31;
    const int h  = blockIdx.z;
    const int m0 = blockIdx.y * 64;
    const int n0 = blockIdx.x * 128;

    const char* A1 = g_A1 + ((size_t)h * NB + m0) * ND;
    const char* A0 = g_A0 + ((size_t)h * NB + m0) * ND;
    const char* B1 = g_B1 + ((size_t)h * NP + n0) * ND;
    const char* B0 = g_B0 + ((size_t)h * NP + n0) * ND;

    // stage: 1536 x 16B chunks (A1 64r | A0 64r | B1 128r | B0 128r), 64B rows
    auto load_stage = [&](int s, int kt) {
        const uint32_t base = sb + (uint32_t)s * STG_BYTES;
        #pragma unroll
        for (int q12 = 0; q12 < 12; q12++) {
            const int q = tid + q12 * 128;
            const int r  = q >> 2;          // 0..383
            const int ch = q & 3;
            const char* gp;
            uint32_t reg_off;
            int rr;
            if (r < 64)       { gp = A1 + (size_t)r * ND;         reg_off = 0;      rr = r; }
            else if (r < 128) { gp = A0 + (size_t)(r - 64) * ND;  reg_off = 4096u;  rr = r - 64; }
            else if (r < 256) { gp = B1 + (size_t)(r - 128) * ND; reg_off = 8192u;  rr = r - 128; }
            else              { gp = B0 + (size_t)(r - 256) * ND; reg_off = 16384u; rr = r - 256; }
            cp16(swz_addr(base + reg_off, rr, ch * 16), gp + kt + ch * 16);
        }
        cp_commit();
    };

    load_stage(0, 0);
    load_stage(1, BK);

    const int wn = wid * 32;

    int acc1[4][4][4];
    int accC[4][4][4];
    #pragma unroll
    for (int a = 0; a < 4; a++)
        #pragma unroll
        for (int b = 0; b < 4; b++)
            #pragma unroll
            for (int c = 0; c < 4; c++) { acc1[a][b][c] = 0; accC[a][b][c] = 0; }

    const int lrow = l & 15;
    const int lcb  = (l >> 4) << 4;

    for (int it = 0; it < NITER; it++) {
        if (it + 2 < NITER) cp_wait<1>(); else cp_wait<0>();
        __syncthreads();

        if (it + 2 < NITER) load_stage((it + 2) % STAGES, (it + 2) * BK);

        const uint32_t base   = sb + (uint32_t)(it % STAGES) * STG_BYTES;
        const uint32_t a1base = base;
        const uint32_t a0base = base + 4096u;
        const uint32_t b1base = base + 8192u;
        const uint32_t b0base = base + 16384u;

        #pragma unroll
        for (int kg = 0; kg < 2; kg++) {
            const int cb = kg * 32 + lcb;
            uint32_t b1_[2][4], b0_[2][4];
            #pragma unroll
            for (int nt = 0; nt < 2; nt++) {
                const int row = wn + nt * 16 + lrow;
                LDSM4(b1_[nt], swz_addr(b1base, row, cb));
                LDSM4(b0_[nt], swz_addr(b0base, row, cb));
            }
            #pragma unroll
            for (int mt = 0; mt < 4; mt++) {
                uint32_t a1_[4], a0_[4];
                const int row = mt * 16 + lrow;
                LDSM4(a1_, swz_addr(a1base, row, cb));
                LDSM4(a0_, swz_addr(a0base, row, cb));
                #pragma unroll
                for (int nt = 0; nt < 2; nt++) {
                    #pragma unroll
                    for (int hf = 0; hf < 2; hf++) {
                        const int n8 = nt * 2 + hf;
                        IMMA16832(acc1[mt][n8], a1_, b1_[nt][hf], b1_[nt][hf + 2]);
                        IMMA16832(accC[mt][n8], a1_, b0_[nt][hf], b0_[nt][hf + 2]);
                        IMMA16832(accC[mt][n8], a0_, b1_[nt][hf], b1_[nt][hf + 2]);
                    }
                }
            }
        }
        __syncthreads();
    }

    // epilogue: logit = 2^-12*acc1 + 2^-20*accC + bias
    float bs0[4], bs1[4];
    #pragma unroll
    for (int n8 = 0; n8 < 4; n8++) {
        const int c0 = n0 + wn + n8 * 8 + (l & 3) * 2;
        bs0[n8] = (c0 < NC)     ? bias[h * NC + c0]     : 0.f;
        bs1[n8] = (c0 + 1 < NC) ? bias[h * NC + c0 + 1] : 0.f;
    }
    #pragma unroll
    for (int mt = 0; mt < 4; mt++) {
        const int r0 = m0 + mt * 16 + (l >> 2);
        #pragma unroll
        for (int n8 = 0; n8 < 4; n8++) {
            const int c0 = n0 + wn + n8 * 8 + (l & 3) * 2;
            if (c0 < NC) {
                float2 v0, v1;
                v0.x = fmaf(S_MAIN, (float)acc1[mt][n8][0], fmaf(S_CORR, (float)accC[mt][n8][0], bs0[n8]));
                v0.y = fmaf(S_MAIN, (float)acc1[mt][n8][1], fmaf(S_CORR, (float)accC[mt][n8][1], bs1[n8]));
                v1.x = fmaf(S_MAIN, (float)acc1[mt][n8][2], fmaf(S_CORR, (float)accC[mt][n8][2], bs0[n8]));
                v1.y = fmaf(S_MAIN, (float)acc1[mt][n8][3], fmaf(S_CORR, (float)accC[mt][n8][3], bs1[n8]));
                *(float2*)&g_logits[((size_t)h * NB + r0) * NC + c0]     = v0;
                *(float2*)&g_logits[((size_t)h * NB + r0 + 8) * NC + c0] = v1;
            }
        }
    }
}

// ------------------------- row stats: single pass, float4 --------------------
__global__ __launch_bounds__(256) void rowstats_k() {
    const int row = blockIdx.x;
    const float4* lr = (const float4*)(g_logits + (size_t)row * NC);
    const int tid = threadIdx.x;

    float4 v = make_float4(-1e30f, -1e30f, -1e30f, -1e30f);
    if (tid < NC / 4) v = lr[tid];

    float vmax = v.x; int imax = tid * 4;
    if (v.y > vmax) { vmax = v.y; imax = tid * 4 + 1; }
    if (v.z > vmax) { vmax = v.z; imax = tid * 4 + 2; }
    if (v.w > vmax) { vmax = v.w; imax = tid * 4 + 3; }

    #pragma unroll
    for (int off = 16; off > 0; off >>= 1) {
        float ov = __shfl_down_sync(0xffffffffu, vmax, off);
        int   oi = __shfl_down_sync(0xffffffffu, imax, off);
        if (ov > vmax || (ov == vmax && oi < imax)) { vmax = ov; imax = oi; }
    }
    __shared__ float swv[8];
    __shared__ int   swi[8];
    const int w = tid >> 5;
    if ((tid & 31) == 0) { swv[w] = vmax; swi[w] = imax; }
    __syncthreads();
    if (tid < 8) {
        vmax = swv[tid]; imax = swi[tid];
        #pragma unroll
        for (int off = 4; off > 0; off >>= 1) {
            float ov = __shfl_down_sync(0xffu, vmax, off);
            int   oi = __shfl_down_sync(0xffu, imax, off);
            if (ov > vmax || (ov == vmax && oi < imax)) { vmax = ov; imax = oi; }
        }
        if (tid == 0) { swv[0] = vmax; swi[0] = imax; }
    }
    __syncthreads();
    const float m = swv[0];

    float sum = __expf(v.x - m) + __expf(v.y - m) + __expf(v.z - m) + __expf(v.w - m);
    #pragma unroll
    for (int off = 16; off > 0; off >>= 1)
        sum += __shfl_down_sync(0xffffffffu, sum, off);
    __shared__ float sws[8];
    if ((tid & 31) == 0) sws[w] = sum;
    __syncthreads();
    if (tid == 0) {
        float s = 0.f;
        #pragma unroll
        for (int i = 0; i < 8; i++) s += sws[i];
        g_conf[row] = 1.f / s;
        g_logZ[row] = m + logf(s);
        g_amax[row] = swi[0];
    }
}

// ------------------------- routing + gather ----------------------------------
__global__ __launch_bounds__(256) void route_k(const int* __restrict__ y_true,
                                               float* __restrict__ out) {
    const int b = blockIdx.x;
    int fh = -1, bh = 0;
    float bc = -1.f;
    #pragma unroll
    for (int hh = 0; hh < NH; hh++) {
        float cv = g_conf[hh * NB + b];
        if (fh < 0 && cv >= TAU) fh = hh;
        if (cv > bc) { bc = cv; bh = hh; }
    }
    const int e = (fh >= 0) ? fh : bh;

    const float* lr = g_logits + ((size_t)e * NB + b) * NC;
    const float4* src = (const float4*)lr;
    float4* dst = (float4*)(out + (size_t)b * NC);
    if (threadIdx.x < NC / 4) dst[threadIdx.x] = src[threadIdx.x];

    if (threadIdx.x == 0) {
        out[(size_t)NB * NC + b] = (float)e;
        const int y = y_true[b];
        g_loss[b] = -(lr[y] - g_logZ[e * NB + b]);
        g_corr[b] = (g_amax[e * NB + b] == y) ? 1.f : 0.f;
    }
}

__global__ __launch_bounds__(512) void final_k(float* __restrict__ out) {
    __shared__ float sl[512];
    __shared__ float sc[512];
    const int t = threadIdx.x;
    sl[t] = g_loss[t];
    sc[t] = g_corr[t];
    __syncthreads();
    for (int s = 256; s > 0; s >>= 1) {
        if (t < s) { sl[t] += sl[t + s]; sc[t] += sc[t + s]; }
        __syncthreads();
    }
    if (t == 0) {
        out[(size_t)NB * NC + NB + 0] = sl[0] / (float)NB;
        out[(size_t)NB * NC + NB + 1] = sc[0] / (float)NB;
    }
}

// ------------------------- launch --------------------------------------------
extern "C" void kernel_launch(void* const* d_in, const int* in_sizes, int n_in,
                              void* d_out, int out_size) {
    const float* feats = (const float*)d_in[0];
    const float* Wt    = (const float*)d_in[1];
    const float* bias  = (const float*)d_in[2];
    const int*   y     = (const int*)d_in[3];
    float* out = (float*)d_out;

    cudaFuncSetAttribute(gemm_mma, cudaFuncAttributeMaxDynamicSharedMemorySize, GSMEM);

    conv_all<<<NA_BLK + 32 * 64 * NH, 256>>>(feats, Wt);
    gemm_mma<<<dim3(8, 8, NH), 128, GSMEM>>>(bias);
    rowstats_k<<<NH * NB, 256>>>();
    route_k<<<NB, 256>>>(y, out);
    final_k<<<1, 512>>>(out);
}

// round 7
// speedup vs baseline: 3.1185x; 3.1185x over previous
#include <cuda_runtime.h>
#include <cuda_bf16.h>
#include <math.h>
#include <stdint.h>

#define NH 6
#define NB 512
#define ND 2048
#define NC 1000
#define NP 1024
#define TAU 0.5f

#define BK 32
#define NITER (ND / BK)          // 64
#define STAGES 3
#define STG_BYTES (24 * 1024)    // Ahi 4K | Alo 4K | Bhi 8K | Blo 8K
#define GSMEM (STAGES * STG_BYTES)

// ------------------------- scratch ------------------------------------------
__device__ __nv_bfloat16 g_Ahi[NH * NB * ND];
__device__ __nv_bfloat16 g_Alo[NH * NB * ND];
__device__ __nv_bfloat16 g_Bhi[NH * NP * ND];   // [h][n][k]
__device__ __nv_bfloat16 g_Blo[NH * NP * ND];
__device__ float g_logits[NH * NB * NC];
__device__ float g_conf[NH * NB];
__device__ float g_logZ[NH * NB];
__device__ int   g_amax[NH * NB];
__device__ float g_loss[NB];
__device__ float g_corr[NB];

// ------------------------- helpers ------------------------------------------
__device__ __forceinline__ uint32_t smem_u32(const void* p) {
    uint32_t a;
    asm("{ .reg .u64 t; cvta.to.shared.u64 t, %1; cvt.u32.u64 %0, t; }" : "=r"(a) : "l"(p));
    return a;
}
__device__ __forceinline__ void cp16(uint32_t dst, const void* src) {
    asm volatile("cp.async.cg.shared.global [%0], [%1], 16;\n" :: "r"(dst), "l"(src) : "memory");
}
__device__ __forceinline__ void cp_commit() {
    asm volatile("cp.async.commit_group;\n" ::: "memory");
}
template<int N> __device__ __forceinline__ void cp_wait() {
    asm volatile("cp.async.wait_group %0;\n" :: "n"(N) : "memory");
}
__device__ __forceinline__ uint32_t swz_addr(uint32_t base, int row, int colb) {
    return base + (uint32_t)(row * 64 + (colb ^ ((row & 6) << 3)));
}
#define LDSM4(r, a) \
    asm volatile("ldmatrix.sync.aligned.m8n8.x4.shared.b16 {%0,%1,%2,%3}, [%4];" \
        : "=r"((r)[0]), "=r"((r)[1]), "=r"((r)[2]), "=r"((r)[3]) : "r"(a))
#define MMA16816(c, a, b0, b1) \
    asm volatile("mma.sync.aligned.m16n8k16.row.col.f32.bf16.bf16.f32 " \
        "{%0,%1,%2,%3}, {%4,%5,%6,%7}, {%8,%9}, {%0,%1,%2,%3};" \
        : "+f"((c)[0]), "+f"((c)[1]), "+f"((c)[2]), "+f"((c)[3]) \
        : "r"((a)[0]), "r"((a)[1]), "r"((a)[2]), "r"((a)[3]), "r"(b0), "r"(b1))

// ------------------------- merged conversion kernel --------------------------
#define NA_BLK (NH * NB * ND / 4 / 256)      // 6144

__global__ __launch_bounds__(256) void conv_all(const float* __restrict__ x,
                                                const float* __restrict__ W) {
    const int tid = threadIdx.x;
    if (blockIdx.x < NA_BLK) {
        const int i = blockIdx.x * 256 + tid;
        float4 v = ((const float4*)x)[i];
        __nv_bfloat16 h0 = __float2bfloat16(v.x), h1 = __float2bfloat16(v.y);
        __nv_bfloat16 h2 = __float2bfloat16(v.z), h3 = __float2bfloat16(v.w);
        __nv_bfloat16 l0 = __float2bfloat16(v.x - __bfloat162float(h0));
        __nv_bfloat16 l1 = __float2bfloat16(v.y - __bfloat162float(h1));
        __nv_bfloat16 l2 = __float2bfloat16(v.z - __bfloat162float(h2));
        __nv_bfloat16 l3 = __float2bfloat16(v.w - __bfloat162float(h3));
        __nv_bfloat162* ph = (__nv_bfloat162*)g_Ahi;
        __nv_bfloat162* pl = (__nv_bfloat162*)g_Alo;
        ph[2*i]   = __nv_bfloat162(h0, h1);
        ph[2*i+1] = __nv_bfloat162(h2, h3);
        pl[2*i]   = __nv_bfloat162(l0, l1);
        pl[2*i+1] = __nv_bfloat162(l2, l3);
        return;
    }
    __shared__ float t[32][33];
    const int bi = blockIdx.x - NA_BLK;
    const int n0 = (bi & 31) * 32;
    const int k0 = ((bi >> 5) & 63) * 32;
    const int h  = bi >> 11;

    const int tx = tid & 31, ty = tid >> 5;
    #pragma unroll
    for (int i = 0; i < 4; i++) {
        int k = k0 + ty + 8 * i;
        int n = n0 + tx;
        t[ty + 8 * i][tx] = (n < NC) ? W[((size_t)h * ND + k) * NC + n] : 0.f;
    }
    __syncthreads();

    const int u  = tid & 127;
    const int nn = u >> 2;
    const int kg = u & 3;
    const int isLo = tid >> 7;
    __nv_bfloat16 vals[8];
    #pragma unroll
    for (int j = 0; j < 8; j++) {
        float v = t[kg * 8 + j][nn];
        __nv_bfloat16 hi = __float2bfloat16(v);
        vals[j] = isLo ? __float2bfloat16(v - __bfloat162float(hi)) : hi;
    }
    __nv_bfloat16* dst = (isLo ? g_Blo : g_Bhi)
                       + ((size_t)h * NP + n0 + nn) * ND + k0 + kg * 8;
    *(uint4*)dst = *(uint4*)vals;
}

// ------------------------- mma.sync GEMM ------------------------------------
// CTA 64(M)x128(N), 4 warps (warp tile 64x32), BK=32, 3-stage cp.async.
__global__ void __launch_bounds__(128, 3) gemm_mma(const float* __restrict__ bias) {
    extern __shared__ char sm[];
    const uint32_t sb = smem_u32(sm);
    const int tid = threadIdx.x;
    const int wid = tid >> 5, l = tid & 31;
    const int h  = blockIdx.z;
    const int m0 = blockIdx.y * 64;
    const int n0 = blockIdx.x * 128;

    const __nv_bfloat16* Ah = g_Ahi + ((size_t)h * NB + m0) * ND;
    const __nv_bfloat16* Al = g_Alo + ((size_t)h * NB + m0) * ND;
    const __nv_bfloat16* Bh = g_Bhi + ((size_t)h * NP + n0) * ND;
    const __nv_bfloat16* Bl = g_Blo + ((size_t)h * NP + n0) * ND;

    // branch-free stage fill: fixed region per unrolled step.
    // 128 threads; per stage: A1 256 chunks (2/thr), A0 256 (2/thr),
    // B1 512 (4/thr), B0 512 (4/thr). chunk = 16B; 64B rows.
    const int r_a  = tid >> 1;          // 0..63  A row
    const int c_a  = (tid & 1) << 1;    // 0 or 2 (chunk pair base)
    const int r_b  = tid >> 1;          // reuse; B rows 0..127 via +64
    auto load_stage = [&](int s, int kt) {
        const uint32_t base = sb + (uint32_t)s * STG_BYTES;
        const __nv_bfloat16* gA1 = Ah + (size_t)r_a * ND + kt;
        const __nv_bfloat16* gA0 = Al + (size_t)r_a * ND + kt;
        #pragma unroll
        for (int j = 0; j < 2; j++) {
            cp16(swz_addr(base,         r_a, (c_a + j) * 16), gA1 + (c_a + j) * 8);
            cp16(swz_addr(base + 4096u, r_a, (c_a + j) * 16), gA0 + (c_a + j) * 8);
        }
        #pragma unroll
        for (int half = 0; half < 2; half++) {
            const int row = r_b + half * 64;
            const __nv_bfloat16* gB1 = Bh + (size_t)row * ND + kt;
            const __nv_bfloat16* gB0 = Bl + (size_t)row * ND + kt;
            #pragma unroll
            for (int j = 0; j < 2; j++) {
                cp16(swz_addr(base + 8192u,  row, (c_a + j) * 16), gB1 + (c_a + j) * 8);
                cp16(swz_addr(base + 16384u, row, (c_a + j) * 16), gB0 + (c_a + j) * 8);
            }
        }
        cp_commit();
    };

    load_stage(0, 0);
    load_stage(1, BK);

    const int wn = wid * 32;

    float acc[4][4][4];
    #pragma unroll
    for (int a = 0; a < 4; a++)
        #pragma unroll
        for (int b = 0; b < 4; b++)
            #pragma unroll
            for (int c = 0; c < 4; c++) acc[a][b][c] = 0.f;

    const int lrow = l & 15;
    const int lcb  = (l >> 4) << 4;

    for (int it = 0; it < NITER; it++) {
        if (it + 2 < NITER) cp_wait<1>(); else cp_wait<0>();
        __syncthreads();

        if (it + 2 < NITER) load_stage((it + 2) % STAGES, (it + 2) * BK);

        const uint32_t base   = sb + (uint32_t)(it % STAGES) * STG_BYTES;
        const uint32_t abase  = base;
        const uint32_t albase = base + 4096u;
        const uint32_t bbase  = base + 8192u;
        const uint32_t blbase = base + 16384u;

        #pragma unroll
        for (int kg = 0; kg < 2; kg++) {
            const int cb = kg * 32 + lcb;
            uint32_t bh_[2][4], bl_[2][4];
            #pragma unroll
            for (int nt = 0; nt < 2; nt++) {
                const int row = wn + nt * 16 + lrow;
                LDSM4(bh_[nt], swz_addr(bbase,  row, cb));
                LDSM4(bl_[nt], swz_addr(blbase, row, cb));
            }
            #pragma unroll
            for (int mt = 0; mt < 4; mt++) {
                uint32_t ah_[4], al_[4];
                const int row = mt * 16 + lrow;
                LDSM4(ah_, swz_addr(abase,  row, cb));
                LDSM4(al_, swz_addr(albase, row, cb));
                #pragma unroll
                for (int nt = 0; nt < 2; nt++) {
                    #pragma unroll
                    for (int hf = 0; hf < 2; hf++) {
                        const int n8 = nt * 2 + hf;
                        MMA16816(acc[mt][n8], ah_, bh_[nt][hf], bh_[nt][hf + 2]);
                        MMA16816(acc[mt][n8], ah_, bl_[nt][hf], bl_[nt][hf + 2]);
                        MMA16816(acc[mt][n8], al_, bh_[nt][hf], bh_[nt][hf + 2]);
                    }
                }
            }
        }
        // NOTE: no trailing __syncthreads — the top-of-loop barrier at iter it+1
        // orders all reads of stage it before any thread's loads into stage
        // (it+3)%3 == it%3 (issued after that barrier).
    }

    // epilogue
    float bs0[4], bs1[4];
    #pragma unroll
    for (int n8 = 0; n8 < 4; n8++) {
        const int c0 = n0 + wn + n8 * 8 + (l & 3) * 2;
        bs0[n8] = (c0 < NC)     ? bias[h * NC + c0]     : 0.f;
        bs1[n8] = (c0 + 1 < NC) ? bias[h * NC + c0 + 1] : 0.f;
    }
    #pragma unroll
    for (int mt = 0; mt < 4; mt++) {
        const int r0 = m0 + mt * 16 + (l >> 2);
        #pragma unroll
        for (int n8 = 0; n8 < 4; n8++) {
            const int c0 = n0 + wn + n8 * 8 + (l & 3) * 2;
            if (c0 < NC) {
                float2 v0 = make_float2(acc[mt][n8][0] + bs0[n8], acc[mt][n8][1] + bs1[n8]);
                float2 v1 = make_float2(acc[mt][n8][2] + bs0[n8], acc[mt][n8][3] + bs1[n8]);
                *(float2*)&g_logits[((size_t)h * NB + r0) * NC + c0]     = v0;
                *(float2*)&g_logits[((size_t)h * NB + r0 + 8) * NC + c0] = v1;
            }
        }
    }
}

// ------------------------- row stats: single pass, float4 --------------------
__global__ __launch_bounds__(256) void rowstats_k() {
    const int row = blockIdx.x;
    const float4* lr = (const float4*)(g_logits + (size_t)row * NC);
    const int tid = threadIdx.x;

    float4 v = make_float4(-1e30f, -1e30f, -1e30f, -1e30f);
    if (tid < NC / 4) v = lr[tid];

    float vmax = v.x; int imax = tid * 4;
    if (v.y > vmax) { vmax = v.y; imax = tid * 4 + 1; }
    if (v.z > vmax) { vmax = v.z; imax = tid * 4 + 2; }
    if (v.w > vmax) { vmax = v.w; imax = tid * 4 + 3; }

    #pragma unroll
    for (int off = 16; off > 0; off >>= 1) {
        float ov = __shfl_down_sync(0xffffffffu, vmax, off);
        int   oi = __shfl_down_sync(0xffffffffu, imax, off);
        if (ov > vmax || (ov == vmax && oi < imax)) { vmax = ov; imax = oi; }
    }
    __shared__ float swv[8];
    __shared__ int   swi[8];
    const int w = tid >> 5;
    if ((tid & 31) == 0) { swv[w] = vmax; swi[w] = imax; }
    __syncthreads();
    if (tid < 8) {
        vmax = swv[tid]; imax = swi[tid];
        #pragma unroll
        for (int off = 4; off > 0; off >>= 1) {
            float ov = __shfl_down_sync(0xffu, vmax, off);
            int   oi = __shfl_down_sync(0xffu, imax, off);
            if (ov > vmax || (ov == vmax && oi < imax)) { vmax = ov; imax = oi; }
        }
        if (tid == 0) { swv[0] = vmax; swi[0] = imax; }
    }
    __syncthreads();
    const float m = swv[0];

    float sum = __expf(v.x - m) + __expf(v.y - m) + __expf(v.z - m) + __expf(v.w - m);
    #pragma unroll
    for (int off = 16; off > 0; off >>= 1)
        sum += __shfl_down_sync(0xffffffffu, sum, off);
    __shared__ float sws[8];
    if ((tid & 31) == 0) sws[w] = sum;
    __syncthreads();
    if (tid == 0) {
        float s = 0.f;
        #pragma unroll
        for (int i = 0; i < 8; i++) s += sws[i];
        g_conf[row] = 1.f / s;
        g_logZ[row] = m + logf(s);
        g_amax[row] = swi[0];
    }
}

// ------------------------- routing + gather ----------------------------------
__global__ __launch_bounds__(256) void route_k(const int* __restrict__ y_true,
                                               float* __restrict__ out) {
    const int b = blockIdx.x;
    int fh = -1, bh = 0;
    float bc = -1.f;
    #pragma unroll
    for (int hh = 0; hh < NH; hh++) {
        float cv = g_conf[hh * NB + b];
        if (fh < 0 && cv >= TAU) fh = hh;
        if (cv > bc) { bc = cv; bh = hh; }
    }
    const int e = (fh >= 0) ? fh : bh;

    const float* lr = g_logits + ((size_t)e * NB + b) * NC;
    const float4* src = (const float4*)lr;
    float4* dst = (float4*)(out + (size_t)b * NC);
    if (threadIdx.x < NC / 4) dst[threadIdx.x] = src[threadIdx.x];

    if (threadIdx.x == 0) {
        out[(size_t)NB * NC + b] = (float)e;
        const int y = y_true[b];
        g_loss[b] = -(lr[y] - g_logZ[e * NB + b]);
        g_corr[b] = (g_amax[e * NB + b] == y) ? 1.f : 0.f;
    }
}

__global__ __launch_bounds__(512) void final_k(float* __restrict__ out) {
    __shared__ float sl[512];
    __shared__ float sc[512];
    const int t = threadIdx.x;
    sl[t] = g_loss[t];
    sc[t] = g_corr[t];
    __syncthreads();
    for (int s = 256; s > 0; s >>= 1) {
        if (t < s) { sl[t] += sl[t + s]; sc[t] += sc[t + s]; }
        __syncthreads();
    }
    if (t == 0) {
        out[(size_t)NB * NC + NB + 0] = sl[0] / (float)NB;
        out[(size_t)NB * NC + NB + 1] = sc[0] / (float)NB;
    }
}

// ------------------------- launch --------------------------------------------
extern "C" void kernel_launch(void* const* d_in, const int* in_sizes, int n_in,
                              void* d_out, int out_size) {
    const float* feats = (const float*)d_in[0];
    const float* Wt    = (const float*)d_in[1];
    const float* bias  = (const float*)d_in[2];
    const int*   y     = (const int*)d_in[3];
    float* out = (float*)d_out;

    cudaFuncSetAttribute(gemm_mma, cudaFuncAttributeMaxDynamicSharedMemorySize, GSMEM);

    conv_all<<<NA_BLK + 32 * 64 * NH, 256>>>(feats, Wt);
    gemm_mma<<<dim3(8, 8, NH), 128, GSMEM>>>(bias);
    rowstats_k<<<NH * NB, 256>>>();
    route_k<<<NB, 256>>>(y, out);
    final_k<<<1, 512>>>(out);
}

// round 8
// speedup vs baseline: 3.7792x; 1.2118x over previous
#include <cuda_runtime.h>
#include <cuda_bf16.h>
#include <math.h>
#include <stdint.h>

#define NH 6
#define NB 512
#define ND 2048
#define NC 1000
#define NP 1024
#define TAU 0.5f

#define BK 32
#define NITER (ND / BK)          // 64
#define STAGES 3
#define STG_BYTES (24 * 1024)    // Ahi 4K | Alo 4K | Bhi 8K | Blo 8K
#define GSMEM (STAGES * STG_BYTES)

// ------------------------- scratch ------------------------------------------
__device__ __nv_bfloat16 g_Ahi[NH * NB * ND];
__device__ __nv_bfloat16 g_Alo[NH * NB * ND];
__device__ __nv_bfloat16 g_Bhi[NH * NP * ND];   // [h][n][k]
__device__ __nv_bfloat16 g_Blo[NH * NP * ND];
__device__ float g_logits[NH * NB * NC];
__device__ float g_conf[NH * NB];
__device__ float g_logZ[NH * NB];
__device__ int   g_amax[NH * NB];
__device__ float g_loss[NB];
__device__ float g_corr[NB];

// ------------------------- helpers ------------------------------------------
__device__ __forceinline__ uint32_t smem_u32(const void* p) {
    uint32_t a;
    asm("{ .reg .u64 t; cvta.to.shared.u64 t, %1; cvt.u32.u64 %0, t; }" : "=r"(a) : "l"(p));
    return a;
}
__device__ __forceinline__ void cp16(uint32_t dst, const void* src) {
    asm volatile("cp.async.cg.shared.global [%0], [%1], 16;\n" :: "r"(dst), "l"(src) : "memory");
}
__device__ __forceinline__ void cp_commit() {
    asm volatile("cp.async.commit_group;\n" ::: "memory");
}
template<int N> __device__ __forceinline__ void cp_wait() {
    asm volatile("cp.async.wait_group %0;\n" :: "n"(N) : "memory");
}
__device__ __forceinline__ uint32_t swz_addr(uint32_t base, int row, int colb) {
    return base + (uint32_t)(row * 64 + (colb ^ ((row & 6) << 3)));
}
#define LDSM4(r, a) \
    asm volatile("ldmatrix.sync.aligned.m8n8.x4.shared.b16 {%0,%1,%2,%3}, [%4];" \
        : "=r"((r)[0]), "=r"((r)[1]), "=r"((r)[2]), "=r"((r)[3]) : "r"(a))
#define MMA16816(c, a, b0, b1) \
    asm volatile("mma.sync.aligned.m16n8k16.row.col.f32.bf16.bf16.f32 " \
        "{%0,%1,%2,%3}, {%4,%5,%6,%7}, {%8,%9}, {%0,%1,%2,%3};" \
        : "+f"((c)[0]), "+f"((c)[1]), "+f"((c)[2]), "+f"((c)[3]) \
        : "r"((a)[0]), "r"((a)[1]), "r"((a)[2]), "r"((a)[3]), "r"(b0), "r"(b1))

// ------------------------- merged conversion kernel --------------------------
#define NA_BLK (NH * NB * ND / 4 / 256)      // 6144

__global__ __launch_bounds__(256) void conv_all(const float* __restrict__ x,
                                                const float* __restrict__ W) {
    const int tid = threadIdx.x;
    if (blockIdx.x < NA_BLK) {
        const int i = blockIdx.x * 256 + tid;
        float4 v = ((const float4*)x)[i];
        __nv_bfloat16 h0 = __float2bfloat16(v.x), h1 = __float2bfloat16(v.y);
        __nv_bfloat16 h2 = __float2bfloat16(v.z), h3 = __float2bfloat16(v.w);
        __nv_bfloat16 l0 = __float2bfloat16(v.x - __bfloat162float(h0));
        __nv_bfloat16 l1 = __float2bfloat16(v.y - __bfloat162float(h1));
        __nv_bfloat16 l2 = __float2bfloat16(v.z - __bfloat162float(h2));
        __nv_bfloat16 l3 = __float2bfloat16(v.w - __bfloat162float(h3));
        __nv_bfloat162* ph = (__nv_bfloat162*)g_Ahi;
        __nv_bfloat162* pl = (__nv_bfloat162*)g_Alo;
        ph[2*i]   = __nv_bfloat162(h0, h1);
        ph[2*i+1] = __nv_bfloat162(h2, h3);
        pl[2*i]   = __nv_bfloat162(l0, l1);
        pl[2*i+1] = __nv_bfloat162(l2, l3);
        return;
    }
    __shared__ float t[32][33];
    const int bi = blockIdx.x - NA_BLK;
    const int n0 = (bi & 31) * 32;
    const int k0 = ((bi >> 5) & 63) * 32;
    const int h  = bi >> 11;

    const int tx = tid & 31, ty = tid >> 5;
    #pragma unroll
    for (int i = 0; i < 4; i++) {
        int k = k0 + ty + 8 * i;
        int n = n0 + tx;
        t[ty + 8 * i][tx] = (n < NC) ? W[((size_t)h * ND + k) * NC + n] : 0.f;
    }
    __syncthreads();

    const int u  = tid & 127;
    const int nn = u >> 2;
    const int kg = u & 3;
    const int isLo = tid >> 7;
    __nv_bfloat16 vals[8];
    #pragma unroll
    for (int j = 0; j < 8; j++) {
        float v = t[kg * 8 + j][nn];
        __nv_bfloat16 hi = __float2bfloat16(v);
        vals[j] = isLo ? __float2bfloat16(v - __bfloat162float(hi)) : hi;
    }
    __nv_bfloat16* dst = (isLo ? g_Blo : g_Bhi)
                       + ((size_t)h * NP + n0 + nn) * ND + k0 + kg * 8;
    *(uint4*)dst = *(uint4*)vals;
}

// ------------------------- mma.sync GEMM ------------------------------------
// CTA 64(M)x128(N), 4 warps (warp tile 64x32), BK=32, 3-stage cp.async.
// Inner loop is TERM-MAJOR: all fragments loaded first, then 3 passes of 16
// independent MMAs each -> dependent accumulator updates are 16 issues apart.
__global__ void __launch_bounds__(128, 3) gemm_mma(const float* __restrict__ bias) {
    extern __shared__ char sm[];
    const uint32_t sb = smem_u32(sm);
    const int tid = threadIdx.x;
    const int wid = tid >> 5, l = tid & 31;
    const int h  = blockIdx.z;
    const int m0 = blockIdx.y * 64;
    const int n0 = blockIdx.x * 128;

    const __nv_bfloat16* Ah = g_Ahi + ((size_t)h * NB + m0) * ND;
    const __nv_bfloat16* Al = g_Alo + ((size_t)h * NB + m0) * ND;
    const __nv_bfloat16* Bh = g_Bhi + ((size_t)h * NP + n0) * ND;
    const __nv_bfloat16* Bl = g_Blo + ((size_t)h * NP + n0) * ND;

    // stage: 1536 x 16B chunks (Ahi 64r | Alo 64r | Bhi 128r | Blo 128r), 64B rows
    auto load_stage = [&](int s, int kt) {
        const uint32_t base = sb + (uint32_t)s * STG_BYTES;
        #pragma unroll
        for (int q12 = 0; q12 < 12; q12++) {
            const int q = tid + q12 * 128;
            const int r  = q >> 2;          // 0..383
            const int ch = q & 3;
            const __nv_bfloat16* gp;
            uint32_t reg_off;
            int rr;
            if (r < 64)       { gp = Ah + (size_t)r * ND;         reg_off = 0;      rr = r; }
            else if (r < 128) { gp = Al + (size_t)(r - 64) * ND;  reg_off = 4096u;  rr = r - 64; }
            else if (r < 256) { gp = Bh + (size_t)(r - 128) * ND; reg_off = 8192u;  rr = r - 128; }
            else              { gp = Bl + (size_t)(r - 256) * ND; reg_off = 16384u; rr = r - 256; }
            cp16(swz_addr(base + reg_off, rr, ch * 16), gp + kt + ch * 8);
        }
        cp_commit();
    };

    load_stage(0, 0);
    load_stage(1, BK);

    const int wn = wid * 32;

    float acc[4][4][4];
    #pragma unroll
    for (int a = 0; a < 4; a++)
        #pragma unroll
        for (int b = 0; b < 4; b++)
            #pragma unroll
            for (int c = 0; c < 4; c++) acc[a][b][c] = 0.f;

    const int lrow = l & 15;
    const int lcb  = (l >> 4) << 4;

    for (int it = 0; it < NITER; it++) {
        if (it + 2 < NITER) cp_wait<1>(); else cp_wait<0>();
        __syncthreads();

        if (it + 2 < NITER) load_stage((it + 2) % STAGES, (it + 2) * BK);

        const uint32_t base   = sb + (uint32_t)(it % STAGES) * STG_BYTES;
        const uint32_t abase  = base;
        const uint32_t albase = base + 4096u;
        const uint32_t bbase  = base + 8192u;
        const uint32_t blbase = base + 16384u;

        #pragma unroll
        for (int kg = 0; kg < 2; kg++) {
            const int cb = kg * 32 + lcb;
            uint32_t bh_[2][4], bl_[2][4];
            uint32_t ah_[4][4], al_[4][4];
            #pragma unroll
            for (int nt = 0; nt < 2; nt++) {
                const int row = wn + nt * 16 + lrow;
                LDSM4(bh_[nt], swz_addr(bbase,  row, cb));
                LDSM4(bl_[nt], swz_addr(blbase, row, cb));
            }
            #pragma unroll
            for (int mt = 0; mt < 4; mt++) {
                const int row = mt * 16 + lrow;
                LDSM4(ah_[mt], swz_addr(abase,  row, cb));
                LDSM4(al_[mt], swz_addr(albase, row, cb));
            }
            // term 1: Ah x Bh  (16 independent MMAs)
            #pragma unroll
            for (int mt = 0; mt < 4; mt++)
                #pragma unroll
                for (int nt = 0; nt < 2; nt++)
                    #pragma unroll
                    for (int hf = 0; hf < 2; hf++)
                        MMA16816(acc[mt][nt * 2 + hf], ah_[mt], bh_[nt][hf], bh_[nt][hf + 2]);
            // term 2: Ah x Bl
            #pragma unroll
            for (int mt = 0; mt < 4; mt++)
                #pragma unroll
                for (int nt = 0; nt < 2; nt++)
                    #pragma unroll
                    for (int hf = 0; hf < 2; hf++)
                        MMA16816(acc[mt][nt * 2 + hf], ah_[mt], bl_[nt][hf], bl_[nt][hf + 2]);
            // term 3: Al x Bh
            #pragma unroll
            for (int mt = 0; mt < 4; mt++)
                #pragma unroll
                for (int nt = 0; nt < 2; nt++)
                    #pragma unroll
                    for (int hf = 0; hf < 2; hf++)
                        MMA16816(acc[mt][nt * 2 + hf], al_[mt], bh_[nt][hf], bh_[nt][hf + 2]);
        }
        __syncthreads();
    }

    // epilogue
    float bs0[4], bs1[4];
    #pragma unroll
    for (int n8 = 0; n8 < 4; n8++) {
        const int c0 = n0 + wn + n8 * 8 + (l & 3) * 2;
        bs0[n8] = (c0 < NC)     ? bias[h * NC + c0]     : 0.f;
        bs1[n8] = (c0 + 1 < NC) ? bias[h * NC + c0 + 1] : 0.f;
    }
    #pragma unroll
    for (int mt = 0; mt < 4; mt++) {
        const int r0 = m0 + mt * 16 + (l >> 2);
        #pragma unroll
        for (int n8 = 0; n8 < 4; n8++) {
            const int c0 = n0 + wn + n8 * 8 + (l & 3) * 2;
            if (c0 < NC) {
                float2 v0 = make_float2(acc[mt][n8][0] + bs0[n8], acc[mt][n8][1] + bs1[n8]);
                float2 v1 = make_float2(acc[mt][n8][2] + bs0[n8], acc[mt][n8][3] + bs1[n8]);
                *(float2*)&g_logits[((size_t)h * NB + r0) * NC + c0]     = v0;
                *(float2*)&g_logits[((size_t)h * NB + r0 + 8) * NC + c0] = v1;
            }
        }
    }
}

// ------------------------- row stats: single pass, float4 --------------------
__global__ __launch_bounds__(256) void rowstats_k() {
    const int row = blockIdx.x;
    const float4* lr = (const float4*)(g_logits + (size_t)row * NC);
    const int tid = threadIdx.x;

    float4 v = make_float4(-1e30f, -1e30f, -1e30f, -1e30f);
    if (tid < NC / 4) v = lr[tid];

    float vmax = v.x; int imax = tid * 4;
    if (v.y > vmax) { vmax = v.y; imax = tid * 4 + 1; }
    if (v.z > vmax) { vmax = v.z; imax = tid * 4 + 2; }
    if (v.w > vmax) { vmax = v.w; imax = tid * 4 + 3; }

    #pragma unroll
    for (int off = 16; off > 0; off >>= 1) {
        float ov = __shfl_down_sync(0xffffffffu, vmax, off);
        int   oi = __shfl_down_sync(0xffffffffu, imax, off);
        if (ov > vmax || (ov == vmax && oi < imax)) { vmax = ov; imax = oi; }
    }
    __shared__ float swv[8];
    __shared__ int   swi[8];
    const int w = tid >> 5;
    if ((tid & 31) == 0) { swv[w] = vmax; swi[w] = imax; }
    __syncthreads();
    if (tid < 8) {
        vmax = swv[tid]; imax = swi[tid];
        #pragma unroll
        for (int off = 4; off > 0; off >>= 1) {
            float ov = __shfl_down_sync(0xffu, vmax, off);
            int   oi = __shfl_down_sync(0xffu, imax, off);
            if (ov > vmax || (ov == vmax && oi < imax)) { vmax = ov; imax = oi; }
        }
        if (tid == 0) { swv[0] = vmax; swi[0] = imax; }
    }
    __syncthreads();
    const float m = swv[0];

    float sum = __expf(v.x - m) + __expf(v.y - m) + __expf(v.z - m) + __expf(v.w - m);
    #pragma unroll
    for (int off = 16; off > 0; off >>= 1)
        sum += __shfl_down_sync(0xffffffffu, sum, off);
    __shared__ float sws[8];
    if ((tid & 31) == 0) sws[w] = sum;
    __syncthreads();
    if (tid == 0) {
        float s = 0.f;
        #pragma unroll
        for (int i = 0; i < 8; i++) s += sws[i];
        g_conf[row] = 1.f / s;
        g_logZ[row] = m + logf(s);
        g_amax[row] = swi[0];
    }
}

// ------------------------- routing + gather ----------------------------------
__global__ __launch_bounds__(256) void route_k(const int* __restrict__ y_true,
                                               float* __restrict__ out) {
    const int b = blockIdx.x;
    int fh = -1, bh = 0;
    float bc = -1.f;
    #pragma unroll
    for (int hh = 0; hh < NH; hh++) {
        float cv = g_conf[hh * NB + b];
        if (fh < 0 && cv >= TAU) fh = hh;
        if (cv > bc) { bc = cv; bh = hh; }
    }
    const int e = (fh >= 0) ? fh : bh;

    const float* lr = g_logits + ((size_t)e * NB + b) * NC;
    const float4* src = (const float4*)lr;
    float4* dst = (float4*)(out + (size_t)b * NC);
    if (threadIdx.x < NC / 4) dst[threadIdx.x] = src[threadIdx.x];

    if (threadIdx.x == 0) {
        out[(size_t)NB * NC + b] = (float)e;
        const int y = y_true[b];
        g_loss[b] = -(lr[y] - g_logZ[e * NB + b]);
        g_corr[b] = (g_amax[e * NB + b] == y) ? 1.f : 0.f;
    }
}

__global__ __launch_bounds__(512) void final_k(float* __restrict__ out) {
    __shared__ float sl[512];
    __shared__ float sc[512];
    const int t = threadIdx.x;
    sl[t] = g_loss[t];
    sc[t] = g_corr[t];
    __syncthreads();
    for (int s = 256; s > 0; s >>= 1) {
        if (t < s) { sl[t] += sl[t + s]; sc[t] += sc[t + s]; }
        __syncthreads();
    }
    if (t == 0) {
        out[(size_t)NB * NC + NB + 0] = sl[0] / (float)NB;
        out[(size_t)NB * NC + NB + 1] = sc[0] / (float)NB;
    }
}

// ------------------------- launch --------------------------------------------
extern "C" void kernel_launch(void* const* d_in, const int* in_sizes, int n_in,
                              void* d_out, int out_size) {
    const float* feats = (const float*)d_in[0];
    const float* Wt    = (const float*)d_in[1];
    const float* bias  = (const float*)d_in[2];
    const int*   y     = (const int*)d_in[3];
    float* out = (float*)d_out;

    cudaFuncSetAttribute(gemm_mma, cudaFuncAttributeMaxDynamicSharedMemorySize, GSMEM);

    conv_all<<<NA_BLK + 32 * 64 * NH, 256>>>(feats, Wt);
    gemm_mma<<<dim3(8, 8, NH), 128, GSMEM>>>(bias);
    rowstats_k<<<NH * NB, 256>>>();
    route_k<<<NB, 256>>>(y, out);
    final_k<<<1, 512>>>(out);
}

// round 9
// speedup vs baseline: 5.1319x; 1.3579x over previous
#include <cuda_runtime.h>
#include <cuda_fp16.h>
#include <math.h>
#include <stdint.h>

#define NH 6
#define NB 512
#define ND 2048
#define NC 1000
#define NP 1024
#define TAU 0.5f

#define BK 32
#define NITER (ND / BK)          // 64
#define STAGES 3
#define STG_BYTES (16 * 1024)    // Ahi 4K | Alo 4K | Bh 8K
#define GSMEM (STAGES * STG_BYTES)

// ------------------------- scratch ------------------------------------------
__device__ __half g_Ahi[NH * NB * ND];
__device__ __half g_Alo[NH * NB * ND];
__device__ __half g_Bh[NH * NP * ND];   // [h][n][k]
__device__ float g_logits[NH * NB * NC];
__device__ float g_conf[NH * NB];
__device__ float g_logZ[NH * NB];
__device__ int   g_amax[NH * NB];
__device__ float g_loss[NB];
__device__ float g_corr[NB];

// ------------------------- helpers ------------------------------------------
__device__ __forceinline__ uint32_t smem_u32(const void* p) {
    uint32_t a;
    asm("{ .reg .u64 t; cvta.to.shared.u64 t, %1; cvt.u32.u64 %0, t; }" : "=r"(a) : "l"(p));
    return a;
}
__device__ __forceinline__ void cp16(uint32_t dst, const void* src) {
    asm volatile("cp.async.cg.shared.global [%0], [%1], 16;\n" :: "r"(dst), "l"(src) : "memory");
}
__device__ __forceinline__ void cp_commit() {
    asm volatile("cp.async.commit_group;\n" ::: "memory");
}
template<int N> __device__ __forceinline__ void cp_wait() {
    asm volatile("cp.async.wait_group %0;\n" :: "n"(N) : "memory");
}
__device__ __forceinline__ uint32_t swz_addr(uint32_t base, int row, int colb) {
    return base + (uint32_t)(row * 64 + (colb ^ ((row & 6) << 3)));
}
#define LDSM4(r, a) \
    asm volatile("ldmatrix.sync.aligned.m8n8.x4.shared.b16 {%0,%1,%2,%3}, [%4];" \
        : "=r"((r)[0]), "=r"((r)[1]), "=r"((r)[2]), "=r"((r)[3]) : "r"(a))
#define MMA16816(c, a, b0, b1) \
    asm volatile("mma.sync.aligned.m16n8k16.row.col.f32.f16.f16.f32 " \
        "{%0,%1,%2,%3}, {%4,%5,%6,%7}, {%8,%9}, {%0,%1,%2,%3};" \
        : "+f"((c)[0]), "+f"((c)[1]), "+f"((c)[2]), "+f"((c)[3]) \
        : "r"((a)[0]), "r"((a)[1]), "r"((a)[2]), "r"((a)[3]), "r"(b0), "r"(b1))

// ------------------------- merged conversion kernel --------------------------
#define NA_BLK (NH * NB * ND / 4 / 256)      // 6144

__global__ __launch_bounds__(256) void conv_all(const float* __restrict__ x,
                                                const float* __restrict__ W) {
    const int tid = threadIdx.x;
    if (blockIdx.x < NA_BLK) {
        const int i = blockIdx.x * 256 + tid;
        float4 v = ((const float4*)x)[i];
        __half h0 = __float2half_rn(v.x), h1 = __float2half_rn(v.y);
        __half h2 = __float2half_rn(v.z), h3 = __float2half_rn(v.w);
        __half l0 = __float2half_rn(v.x - __half2float(h0));
        __half l1 = __float2half_rn(v.y - __half2float(h1));
        __half l2 = __float2half_rn(v.z - __half2float(h2));
        __half l3 = __float2half_rn(v.w - __half2float(h3));
        __half2* ph = (__half2*)g_Ahi;
        __half2* pl = (__half2*)g_Alo;
        ph[2*i]   = __halves2half2(h0, h1);
        ph[2*i+1] = __halves2half2(h2, h3);
        pl[2*i]   = __halves2half2(l0, l1);
        pl[2*i+1] = __halves2half2(l2, l3);
        return;
    }
    // B role: W [h][k][n] fp32 -> g_Bh [h][n(1024)][k] fp16
    __shared__ float t[32][33];
    const int bi = blockIdx.x - NA_BLK;
    const int n0 = (bi & 31) * 32;
    const int k0 = ((bi >> 5) & 63) * 32;
    const int h  = bi >> 11;

    const int tx = tid & 31, ty = tid >> 5;
    #pragma unroll
    for (int i = 0; i < 4; i++) {
        int k = k0 + ty + 8 * i;
        int n = n0 + tx;
        t[ty + 8 * i][tx] = (n < NC) ? W[((size_t)h * ND + k) * NC + n] : 0.f;
    }
    __syncthreads();

    // 128 threads emit one 16B store each (32 n-rows x 4 k-groups)
    if (tid < 128) {
        const int nn = tid >> 2;
        const int kg = tid & 3;
        __half vals[8];
        #pragma unroll
        for (int j = 0; j < 8; j++)
            vals[j] = __float2half_rn(t[kg * 8 + j][nn]);
        __half* dst = g_Bh + ((size_t)h * NP + n0 + nn) * ND + k0 + kg * 8;
        *(uint4*)dst = *(uint4*)vals;
    }
}

// ------------------------- mma.sync GEMM ------------------------------------
// CTA 64(M)x128(N), 4 warps (warp tile 64x32), BK=32, 3-stage cp.async.
// 2-term fp16 limb scheme: acc += Ah*Bh + Al*Bh  (B fragments shared).
__global__ void __launch_bounds__(128, 3) gemm_mma(const float* __restrict__ bias) {
    extern __shared__ char sm[];
    const uint32_t sb = smem_u32(sm);
    const int tid = threadIdx.x;
    const int wid = tid >> 5, l = tid & 31;
    const int h  = blockIdx.z;
    const int m0 = blockIdx.y * 64;
    const int n0 = blockIdx.x * 128;

    const __half* Ah = g_Ahi + ((size_t)h * NB + m0) * ND;
    const __half* Al = g_Alo + ((size_t)h * NB + m0) * ND;
    const __half* Bh = g_Bh  + ((size_t)h * NP + n0) * ND;

    // stage: 1024 x 16B chunks (Ahi 64r | Alo 64r | Bh 128r), 64B rows
    auto load_stage = [&](int s, int kt) {
        const uint32_t base = sb + (uint32_t)s * STG_BYTES;
        #pragma unroll
        for (int q8 = 0; q8 < 8; q8++) {
            const int q = tid + q8 * 128;
            const int r  = q >> 2;          // 0..255
            const int ch = q & 3;
            const __half* gp;
            uint32_t reg_off;
            int rr;
            if (r < 64)       { gp = Ah + (size_t)r * ND;        reg_off = 0;     rr = r; }
            else if (r < 128) { gp = Al + (size_t)(r - 64) * ND; reg_off = 4096u; rr = r - 64; }
            else              { gp = Bh + (size_t)(r - 128) * ND; reg_off = 8192u; rr = r - 128; }
            cp16(swz_addr(base + reg_off, rr, ch * 16), gp + kt + ch * 8);
        }
        cp_commit();
    };

    load_stage(0, 0);
    load_stage(1, BK);

    const int wn = wid * 32;

    float acc[4][4][4];
    #pragma unroll
    for (int a = 0; a < 4; a++)
        #pragma unroll
        for (int b = 0; b < 4; b++)
            #pragma unroll
            for (int c = 0; c < 4; c++) acc[a][b][c] = 0.f;

    const int lrow = l & 15;
    const int lcb  = (l >> 4) << 4;

    for (int it = 0; it < NITER; it++) {
        if (it + 2 < NITER) cp_wait<1>(); else cp_wait<0>();
        __syncthreads();

        if (it + 2 < NITER) load_stage((it + 2) % STAGES, (it + 2) * BK);

        const uint32_t base   = sb + (uint32_t)(it % STAGES) * STG_BYTES;
        const uint32_t abase  = base;
        const uint32_t albase = base + 4096u;
        const uint32_t bbase  = base + 8192u;

        #pragma unroll
        for (int kg = 0; kg < 2; kg++) {
            const int cb = kg * 32 + lcb;
            uint32_t bh_[2][4];
            uint32_t ah_[4][4], al_[4][4];
            #pragma unroll
            for (int nt = 0; nt < 2; nt++) {
                const int row = wn + nt * 16 + lrow;
                LDSM4(bh_[nt], swz_addr(bbase, row, cb));
            }
            #pragma unroll
            for (int mt = 0; mt < 4; mt++) {
                const int row = mt * 16 + lrow;
                LDSM4(ah_[mt], swz_addr(abase,  row, cb));
                LDSM4(al_[mt], swz_addr(albase, row, cb));
            }
            // term 1: Ah x Bh (16 independent MMAs)
            #pragma unroll
            for (int mt = 0; mt < 4; mt++)
                #pragma unroll
                for (int nt = 0; nt < 2; nt++)
                    #pragma unroll
                    for (int hf = 0; hf < 2; hf++)
                        MMA16816(acc[mt][nt * 2 + hf], ah_[mt], bh_[nt][hf], bh_[nt][hf + 2]);
            // term 2: Al x Bh
            #pragma unroll
            for (int mt = 0; mt < 4; mt++)
                #pragma unroll
                for (int nt = 0; nt < 2; nt++)
                    #pragma unroll
                    for (int hf = 0; hf < 2; hf++)
                        MMA16816(acc[mt][nt * 2 + hf], al_[mt], bh_[nt][hf], bh_[nt][hf + 2]);
        }
        __syncthreads();
    }

    // epilogue
    float bs0[4], bs1[4];
    #pragma unroll
    for (int n8 = 0; n8 < 4; n8++) {
        const int c0 = n0 + wn + n8 * 8 + (l & 3) * 2;
        bs0[n8] = (c0 < NC)     ? bias[h * NC + c0]     : 0.f;
        bs1[n8] = (c0 + 1 < NC) ? bias[h * NC + c0 + 1] : 0.f;
    }
    #pragma unroll
    for (int mt = 0; mt < 4; mt++) {
        const int r0 = m0 + mt * 16 + (l >> 2);
        #pragma unroll
        for (int n8 = 0; n8 < 4; n8++) {
            const int c0 = n0 + wn + n8 * 8 + (l & 3) * 2;
            if (c0 < NC) {
                float2 v0 = make_float2(acc[mt][n8][0] + bs0[n8], acc[mt][n8][1] + bs1[n8]);
                float2 v1 = make_float2(acc[mt][n8][2] + bs0[n8], acc[mt][n8][3] + bs1[n8]);
                *(float2*)&g_logits[((size_t)h * NB + r0) * NC + c0]     = v0;
                *(float2*)&g_logits[((size_t)h * NB + r0 + 8) * NC + c0] = v1;
            }
        }
    }
}

// ------------------------- row stats: single pass, float4 --------------------
__global__ __launch_bounds__(256) void rowstats_k() {
    const int row = blockIdx.x;
    const float4* lr = (const float4*)(g_logits + (size_t)row * NC);
    const int tid = threadIdx.x;

    float4 v = make_float4(-1e30f, -1e30f, -1e30f, -1e30f);
    if (tid < NC / 4) v = lr[tid];

    float vmax = v.x; int imax = tid * 4;
    if (v.y > vmax) { vmax = v.y; imax = tid * 4 + 1; }
    if (v.z > vmax) { vmax = v.z; imax = tid * 4 + 2; }
    if (v.w > vmax) { vmax = v.w; imax = tid * 4 + 3; }

    #pragma unroll
    for (int off = 16; off > 0; off >>= 1) {
        float ov = __shfl_down_sync(0xffffffffu, vmax, off);
        int   oi = __shfl_down_sync(0xffffffffu, imax, off);
        if (ov > vmax || (ov == vmax && oi < imax)) { vmax = ov; imax = oi; }
    }
    __shared__ float swv[8];
    __shared__ int   swi[8];
    const int w = tid >> 5;
    if ((tid & 31) == 0) { swv[w] = vmax; swi[w] = imax; }
    __syncthreads();
    if (tid < 8) {
        vmax = swv[tid]; imax = swi[tid];
        #pragma unroll
        for (int off = 4; off > 0; off >>= 1) {
            float ov = __shfl_down_sync(0xffu, vmax, off);
            int   oi = __shfl_down_sync(0xffu, imax, off);
            if (ov > vmax || (ov == vmax && oi < imax)) { vmax = ov; imax = oi; }
        }
        if (tid == 0) { swv[0] = vmax; swi[0] = imax; }
    }
    __syncthreads();
    const float m = swv[0];

    float sum = __expf(v.x - m) + __expf(v.y - m) + __expf(v.z - m) + __expf(v.w - m);
    #pragma unroll
    for (int off = 16; off > 0; off >>= 1)
        sum += __shfl_down_sync(0xffffffffu, sum, off);
    __shared__ float sws[8];
    if ((tid & 31) == 0) sws[w] = sum;
    __syncthreads();
    if (tid == 0) {
        float s = 0.f;
        #pragma unroll
        for (int i = 0; i < 8; i++) s += sws[i];
        g_conf[row] = 1.f / s;
        g_logZ[row] = m + logf(s);
        g_amax[row] = swi[0];
    }
}

// ------------------------- routing + gather ----------------------------------
__global__ __launch_bounds__(256) void route_k(const int* __restrict__ y_true,
                                               float* __restrict__ out) {
    const int b = blockIdx.x;
    int fh = -1, bh = 0;
    float bc = -1.f;
    #pragma unroll
    for (int hh = 0; hh < NH; hh++) {
        float cv = g_conf[hh * NB + b];
        if (fh < 0 && cv >= TAU) fh = hh;
        if (cv > bc) { bc = cv; bh = hh; }
    }
    const int e = (fh >= 0) ? fh : bh;

    const float* lr = g_logits + ((size_t)e * NB + b) * NC;
    const float4* src = (const float4*)lr;
    float4* dst = (float4*)(out + (size_t)b * NC);
    if (threadIdx.x < NC / 4) dst[threadIdx.x] = src[threadIdx.x];

    if (threadIdx.x == 0) {
        out[(size_t)NB * NC + b] = (float)e;
        const int y = y_true[b];
        g_loss[b] = -(lr[y] - g_logZ[e * NB + b]);
        g_corr[b] = (g_amax[e * NB + b] == y) ? 1.f : 0.f;
    }
}

__global__ __launch_bounds__(512) void final_k(float* __restrict__ out) {
    __shared__ float sl[512];
    __shared__ float sc[512];
    const int t = threadIdx.x;
    sl[t] = g_loss[t];
    sc[t] = g_corr[t];
    __syncthreads();
    for (int s = 256; s > 0; s >>= 1) {
        if (t < s) { sl[t] += sl[t + s]; sc[t] += sc[t + s]; }
        __syncthreads();
    }
    if (t == 0) {
        out[(size_t)NB * NC + NB + 0] = sl[0] / (float)NB;
        out[(size_t)NB * NC + NB + 1] = sc[0] / (float)NB;
    }
}

// ------------------------- launch --------------------------------------------
extern "C" void kernel_launch(void* const* d_in, const int* in_sizes, int n_in,
                              void* d_out, int out_size) {
    const float* feats = (const float*)d_in[0];
    const float* Wt    = (const float*)d_in[1];
    const float* bias  = (const float*)d_in[2];
    const int*   y     = (const int*)d_in[3];
    float* out = (float*)d_out;

    cudaFuncSetAttribute(gemm_mma, cudaFuncAttributeMaxDynamicSharedMemorySize, GSMEM);

    conv_all<<<NA_BLK + 32 * 64 * NH, 256>>>(feats, Wt);
    gemm_mma<<<dim3(8, 8, NH), 128, GSMEM>>>(bias);
    rowstats_k<<<NH * NB, 256>>>();
    route_k<<<NB, 256>>>(y, out);
    final_k<<<1, 512>>>(out);
}

// round 10
// speedup vs baseline: 7.4274x; 1.4473x over previous
#include <cuda_runtime.h>
#include <cuda_fp16.h>
#include <math.h>
#include <stdint.h>

#define NH 6
#define NB 512
#define ND 2048
#define NC 1000
#define NP 1024
#define TAU 0.5f

#define BK 32
#define NITER (ND / BK)          // 64
#define STAGES 3
#define STG_BYTES (12 * 1024)    // Ah 4K | Bh 8K
#define GSMEM (STAGES * STG_BYTES)

// ------------------------- scratch ------------------------------------------
__device__ __half g_Ah[NH * NB * ND];
__device__ __half g_Bh[NH * NP * ND];   // [h][n][k]
__device__ float g_logits[NH * NB * NC];
__device__ float g_conf[NH * NB];
__device__ float g_logZ[NH * NB];
__device__ int   g_amax[NH * NB];
__device__ float g_loss[NB];
__device__ float g_corr[NB];

// ------------------------- helpers ------------------------------------------
__device__ __forceinline__ uint32_t smem_u32(const void* p) {
    uint32_t a;
    asm("{ .reg .u64 t; cvta.to.shared.u64 t, %1; cvt.u32.u64 %0, t; }" : "=r"(a) : "l"(p));
    return a;
}
__device__ __forceinline__ void cp16(uint32_t dst, const void* src) {
    asm volatile("cp.async.cg.shared.global [%0], [%1], 16;\n" :: "r"(dst), "l"(src) : "memory");
}
__device__ __forceinline__ void cp_commit() {
    asm volatile("cp.async.commit_group;\n" ::: "memory");
}
template<int N> __device__ __forceinline__ void cp_wait() {
    asm volatile("cp.async.wait_group %0;\n" :: "n"(N) : "memory");
}
__device__ __forceinline__ uint32_t swz_addr(uint32_t base, int row, int colb) {
    return base + (uint32_t)(row * 64 + (colb ^ ((row & 6) << 3)));
}
#define LDSM4(r, a) \
    asm volatile("ldmatrix.sync.aligned.m8n8.x4.shared.b16 {%0,%1,%2,%3}, [%4];" \
        : "=r"((r)[0]), "=r"((r)[1]), "=r"((r)[2]), "=r"((r)[3]) : "r"(a))
#define MMA16816(c, a, b0, b1) \
    asm volatile("mma.sync.aligned.m16n8k16.row.col.f32.f16.f16.f32 " \
        "{%0,%1,%2,%3}, {%4,%5,%6,%7}, {%8,%9}, {%0,%1,%2,%3};" \
        : "+f"((c)[0]), "+f"((c)[1]), "+f"((c)[2]), "+f"((c)[3]) \
        : "r"((a)[0]), "r"((a)[1]), "r"((a)[2]), "r"((a)[3]), "r"(b0), "r"(b1))

// ------------------------- merged conversion kernel --------------------------
#define NA_BLK (NH * NB * ND / 4 / 256)      // 6144

__global__ __launch_bounds__(256) void conv_all(const float* __restrict__ x,
                                                const float* __restrict__ W) {
    const int tid = threadIdx.x;
    if (blockIdx.x < NA_BLK) {
        const int i = blockIdx.x * 256 + tid;
        float4 v = ((const float4*)x)[i];
        __half2* ph = (__half2*)g_Ah;
        ph[2*i]   = __halves2half2(__float2half_rn(v.x), __float2half_rn(v.y));
        ph[2*i+1] = __halves2half2(__float2half_rn(v.z), __float2half_rn(v.w));
        return;
    }
    // B role: W [h][k][n] fp32 -> g_Bh [h][n(1024)][k] fp16
    __shared__ float t[32][33];
    const int bi = blockIdx.x - NA_BLK;
    const int n0 = (bi & 31) * 32;
    const int k0 = ((bi >> 5) & 63) * 32;
    const int h  = bi >> 11;

    const int tx = tid & 31, ty = tid >> 5;
    #pragma unroll
    for (int i = 0; i < 4; i++) {
        int k = k0 + ty + 8 * i;
        int n = n0 + tx;
        t[ty + 8 * i][tx] = (n < NC) ? W[((size_t)h * ND + k) * NC + n] : 0.f;
    }
    __syncthreads();

    if (tid < 128) {
        const int nn = tid >> 2;
        const int kg = tid & 3;
        __half vals[8];
        #pragma unroll
        for (int j = 0; j < 8; j++)
            vals[j] = __float2half_rn(t[kg * 8 + j][nn]);
        __half* dst = g_Bh + ((size_t)h * NP + n0 + nn) * ND + k0 + kg * 8;
        *(uint4*)dst = *(uint4*)vals;
    }
}

// ------------------------- mma.sync GEMM ------------------------------------
// CTA 64(M)x128(N), 4 warps (warp tile 64x32), BK=32, 3-stage cp.async, occ 4.
// One-term fp16: acc += Ah*Bh.
__global__ void __launch_bounds__(128, 4) gemm_mma(const float* __restrict__ bias) {
    extern __shared__ char sm[];
    const uint32_t sb = smem_u32(sm);
    const int tid = threadIdx.x;
    const int wid = tid >> 5, l = tid & 31;
    const int h  = blockIdx.z;
    const int m0 = blockIdx.y * 64;
    const int n0 = blockIdx.x * 128;

    const __half* Ah = g_Ah + ((size_t)h * NB + m0) * ND;
    const __half* Bh = g_Bh + ((size_t)h * NP + n0) * ND;

    // stage: 768 x 16B chunks (Ah 64r | Bh 128r), 64B rows -> 6 per thread
    auto load_stage = [&](int s, int kt) {
        const uint32_t base = sb + (uint32_t)s * STG_BYTES;
        #pragma unroll
        for (int q6 = 0; q6 < 6; q6++) {
            const int q = tid + q6 * 128;
            const int r  = q >> 2;          // 0..191
            const int ch = q & 3;
            const __half* gp;
            uint32_t reg_off;
            int rr;
            if (r < 64) { gp = Ah + (size_t)r * ND;        reg_off = 0;     rr = r; }
            else        { gp = Bh + (size_t)(r - 64) * ND; reg_off = 4096u; rr = r - 64; }
            cp16(swz_addr(base + reg_off, rr, ch * 16), gp + kt + ch * 8);
        }
        cp_commit();
    };

    load_stage(0, 0);
    load_stage(1, BK);

    const int wn = wid * 32;

    float acc[4][4][4];
    #pragma unroll
    for (int a = 0; a < 4; a++)
        #pragma unroll
        for (int b = 0; b < 4; b++)
            #pragma unroll
            for (int c = 0; c < 4; c++) acc[a][b][c] = 0.f;

    const int lrow = l & 15;
    const int lcb  = (l >> 4) << 4;

    for (int it = 0; it < NITER; it++) {
        if (it + 2 < NITER) cp_wait<1>(); else cp_wait<0>();
        __syncthreads();

        if (it + 2 < NITER) load_stage((it + 2) % STAGES, (it + 2) * BK);

        const uint32_t base  = sb + (uint32_t)(it % STAGES) * STG_BYTES;
        const uint32_t abase = base;
        const uint32_t bbase = base + 4096u;

        #pragma unroll
        for (int kg = 0; kg < 2; kg++) {
            const int cb = kg * 32 + lcb;
            uint32_t bh_[2][4];
            uint32_t ah_[4][4];
            #pragma unroll
            for (int nt = 0; nt < 2; nt++) {
                const int row = wn + nt * 16 + lrow;
                LDSM4(bh_[nt], swz_addr(bbase, row, cb));
            }
            #pragma unroll
            for (int mt = 0; mt < 4; mt++) {
                const int row = mt * 16 + lrow;
                LDSM4(ah_[mt], swz_addr(abase, row, cb));
            }
            #pragma unroll
            for (int mt = 0; mt < 4; mt++)
                #pragma unroll
                for (int nt = 0; nt < 2; nt++)
                    #pragma unroll
                    for (int hf = 0; hf < 2; hf++)
                        MMA16816(acc[mt][nt * 2 + hf], ah_[mt], bh_[nt][hf], bh_[nt][hf + 2]);
        }
        __syncthreads();
    }

    // epilogue
    float bs0[4], bs1[4];
    #pragma unroll
    for (int n8 = 0; n8 < 4; n8++) {
        const int c0 = n0 + wn + n8 * 8 + (l & 3) * 2;
        bs0[n8] = (c0 < NC)     ? bias[h * NC + c0]     : 0.f;
        bs1[n8] = (c0 + 1 < NC) ? bias[h * NC + c0 + 1] : 0.f;
    }
    #pragma unroll
    for (int mt = 0; mt < 4; mt++) {
        const int r0 = m0 + mt * 16 + (l >> 2);
        #pragma unroll
        for (int n8 = 0; n8 < 4; n8++) {
            const int c0 = n0 + wn + n8 * 8 + (l & 3) * 2;
            if (c0 < NC) {
                float2 v0 = make_float2(acc[mt][n8][0] + bs0[n8], acc[mt][n8][1] + bs1[n8]);
                float2 v1 = make_float2(acc[mt][n8][2] + bs0[n8], acc[mt][n8][3] + bs1[n8]);
                *(float2*)&g_logits[((size_t)h * NB + r0) * NC + c0]     = v0;
                *(float2*)&g_logits[((size_t)h * NB + r0 + 8) * NC + c0] = v1;
            }
        }
    }
}

// ------------------------- row stats: single pass, float4 --------------------
__global__ __launch_bounds__(256) void rowstats_k() {
    const int row = blockIdx.x;
    const float4* lr = (const float4*)(g_logits + (size_t)row * NC);
    const int tid = threadIdx.x;

    float4 v = make_float4(-1e30f, -1e30f, -1e30f, -1e30f);
    if (tid < NC / 4) v = lr[tid];

    float vmax = v.x; int imax = tid * 4;
    if (v.y > vmax) { vmax = v.y; imax = tid * 4 + 1; }
    if (v.z > vmax) { vmax = v.z; imax = tid * 4 + 2; }
    if (v.w > vmax) { vmax = v.w; imax = tid * 4 + 3; }

    #pragma unroll
    for (int off = 16; off > 0; off >>= 1) {
        float ov = __shfl_down_sync(0xffffffffu, vmax, off);
        int   oi = __shfl_down_sync(0xffffffffu, imax, off);
        if (ov > vmax || (ov == vmax && oi < imax)) { vmax = ov; imax = oi; }
    }
    __shared__ float swv[8];
    __shared__ int   swi[8];
    const int w = tid >> 5;
    if ((tid & 31) == 0) { swv[w] = vmax; swi[w] = imax; }
    __syncthreads();
    if (tid < 8) {
        vmax = swv[tid]; imax = swi[tid];
        #pragma unroll
        for (int off = 4; off > 0; off >>= 1) {
            float ov = __shfl_down_sync(0xffu, vmax, off);
            int   oi = __shfl_down_sync(0xffu, imax, off);
            if (ov > vmax || (ov == vmax && oi < imax)) { vmax = ov; imax = oi; }
        }
        if (tid == 0) { swv[0] = vmax; swi[0] = imax; }
    }
    __syncthreads();
    const float m = swv[0];

    float sum = __expf(v.x - m) + __expf(v.y - m) + __expf(v.z - m) + __expf(v.w - m);
    #pragma unroll
    for (int off = 16; off > 0; off >>= 1)
        sum += __shfl_down_sync(0xffffffffu, sum, off);
    __shared__ float sws[8];
    if ((tid & 31) == 0) sws[w] = sum;
    __syncthreads();
    if (tid == 0) {
        float s = 0.f;
        #pragma unroll
        for (int i = 0; i < 8; i++) s += sws[i];
        g_conf[row] = 1.f / s;
        g_logZ[row] = m + logf(s);
        g_amax[row] = swi[0];
    }
}

// ------------------------- routing + gather ----------------------------------
__global__ __launch_bounds__(256) void route_k(const int* __restrict__ y_true,
                                               float* __restrict__ out) {
    const int b = blockIdx.x;
    int fh = -1, bh = 0;
    float bc = -1.f;
    #pragma unroll
    for (int hh = 0; hh < NH; hh++) {
        float cv = g_conf[hh * NB + b];
        if (fh < 0 && cv >= TAU) fh = hh;
        if (cv > bc) { bc = cv; bh = hh; }
    }
    const int e = (fh >= 0) ? fh : bh;

    const float* lr = g_logits + ((size_t)e * NB + b) * NC;
    const float4* src = (const float4*)lr;
    float4* dst = (float4*)(out + (size_t)b * NC);
    if (threadIdx.x < NC / 4) dst[threadIdx.x] = src[threadIdx.x];

    if (threadIdx.x == 0) {
        out[(size_t)NB * NC + b] = (float)e;
        const int y = y_true[b];
        g_loss[b] = -(lr[y] - g_logZ[e * NB + b]);
        g_corr[b] = (g_amax[e * NB + b] == y) ? 1.f : 0.f;
    }
}

__global__ __launch_bounds__(512) void final_k(float* __restrict__ out) {
    __shared__ float sl[512];
    __shared__ float sc[512];
    const int t = threadIdx.x;
    sl[t] = g_loss[t];
    sc[t] = g_corr[t];
    __syncthreads();
    for (int s = 256; s > 0; s >>= 1) {
        if (t < s) { sl[t] += sl[t + s]; sc[t] += sc[t + s]; }
        __syncthreads();
    }
    if (t == 0) {
        out[(size_t)NB * NC + NB + 0] = sl[0] / (float)NB;
        out[(size_t)NB * NC + NB + 1] = sc[0] / (float)NB;
    }
}

// ------------------------- launch --------------------------------------------
extern "C" void kernel_launch(void* const* d_in, const int* in_sizes, int n_in,
                              void* d_out, int out_size) {
    const float* feats = (const float*)d_in[0];
    const float* Wt    = (const float*)d_in[1];
    const float* bias  = (const float*)d_in[2];
    const int*   y     = (const int*)d_in[3];
    float* out = (float*)d_out;

    cudaFuncSetAttribute(gemm_mma, cudaFuncAttributeMaxDynamicSharedMemorySize, GSMEM);

    conv_all<<<NA_BLK + 32 * 64 * NH, 256>>>(feats, Wt);
    gemm_mma<<<dim3(8, 8, NH), 128, GSMEM>>>(bias);
    rowstats_k<<<NH * NB, 256>>>();
    route_k<<<NB, 256>>>(y, out);
    final_k<<<1, 512>>>(out);
}